// round 8
// baseline (speedup 1.0000x reference)
#include <cuda_runtime.h>

#define NN 100000

typedef unsigned long long u64;

// ---------------- scratch (device globals) ----------------
__device__ float g_pm[(size_t)NN * 64];
__device__ float g_pg[(size_t)NN * 64];
__device__ float g_sum_m[(size_t)NN * 64];
__device__ float g_sum_g[(size_t)NN * 64];
__device__ float g_pos[NN];
__device__ float g_cntm[NN];
__device__ float g_cntg[NN];
__device__ float g_h[(size_t)NN * 128];
__device__ int   g_np[2];          // [0]=nm, [1]=ng
__device__ int   g_perm_m[NN];
__device__ int   g_perm_g[NN];
__device__ float g_Cm[65 * 64];
__device__ float g_Cg[65 * 64];
__device__ float g_A[65 * 128];
__device__ float g_B[65 * 128];
__device__ float g_knots[64];

__device__ __forceinline__ float leaky(float x) { return x > 0.f ? x : 0.1f * x; }

// ---- packed f32x2 helpers ----
__device__ __forceinline__ u64 pack2(float x, float y) {
    u64 r; asm("mov.b64 %0,{%1,%2};" : "=l"(r) : "f"(x), "f"(y)); return r;
}
__device__ __forceinline__ void unpack2(u64 v, float& x, float& y) {
    asm("mov.b64 {%0,%1},%2;" : "=f"(x), "=f"(y) : "l"(v));
}
__device__ __forceinline__ void fma2(u64& acc, u64 a, u64 b) {
    asm("fma.rn.f32x2 %0,%1,%2,%0;" : "+l"(acc) : "l"(a), "l"(b));
}

// one input feature per node (2 nodes) into 64-wide accumulators (32 u64 each)
__device__ __forceinline__ void l1in2(u64* ha, u64* hb, float xa_, float xb_,
                                      const float* w) {
    u64 xa = pack2(xa_, xa_), xb = pack2(xb_, xb_);
    const ulonglong2* wp = (const ulonglong2*)w;
#pragma unroll
    for (int i = 0; i < 16; i++) {
        ulonglong2 ww = wp[i];
        fma2(ha[2 * i], xa, ww.x);
        fma2(ha[2 * i + 1], xa, ww.y);
        fma2(hb[2 * i], xb, ww.x);
        fma2(hb[2 * i + 1], xb, ww.y);
    }
}

// 64 hidden (activated, packed) x 2 nodes -> 16 outputs at column j0 of [64,STRIDE]
// aa/ab: 8 u64 each (low register pressure -> 3 blocks/SM)
template <int STRIDE>
__device__ __forceinline__ void layer2_c16(
    const u64* ha, const u64* hb, const float* w2, const float* b2, int j0,
    u64* aa, u64* ab)
{
    const u64* bp = (const u64*)(b2 + j0);
#pragma unroll
    for (int i = 0; i < 8; i++) { aa[i] = bp[i]; ab[i] = bp[i]; }
#pragma unroll 4
    for (int kk = 0; kk < 32; kk++) {
        float a0, a1, b0, b1;
        unpack2(ha[kk], a0, a1);
        unpack2(hb[kk], b0, b1);
        u64 xa0 = pack2(a0, a0), xa1 = pack2(a1, a1);
        u64 xb0 = pack2(b0, b0), xb1 = pack2(b1, b1);
        const ulonglong2* w0 = (const ulonglong2*)(w2 + (size_t)(2 * kk) * STRIDE + j0);
        const ulonglong2* w1 = (const ulonglong2*)(w2 + (size_t)(2 * kk + 1) * STRIDE + j0);
#pragma unroll
        for (int q = 0; q < 4; q++) {
            ulonglong2 w = w0[q];
            fma2(aa[2 * q], xa0, w.x); fma2(aa[2 * q + 1], xa0, w.y);
            fma2(ab[2 * q], xb0, w.x); fma2(ab[2 * q + 1], xb0, w.y);
        }
#pragma unroll
        for (int q = 0; q < 4; q++) {
            ulonglong2 w = w1[q];
            fma2(aa[2 * q], xa1, w.x); fma2(aa[2 * q + 1], xa1, w.y);
            fma2(ab[2 * q], xb1, w.x); fma2(ab[2 * q + 1], xb1, w.y);
        }
    }
}

__device__ __forceinline__ void leaky_pack(u64* h2) {
#pragma unroll
    for (int i = 0; i < 32; i++) {
        float a, b; unpack2(h2[i], a, b);
        h2[i] = pack2(leaky(a), leaky(b));
    }
}

// ---------------- KC: composed projections Cm, Cg (tiny, must precede k_pre) ------
__global__ void k_compose(
    const float* __restrict__ piw2, const float* __restrict__ pib2,
    const float* __restrict__ nmw1, const float* __restrict__ ngw1)
{
    int i = blockIdx.x;       // 0..64
    int gsel = blockIdx.y;    // 0=m 1=g
    int j = threadIdx.x;      // 0..63
    const float* W = gsel ? ngw1 : nmw1;
    const float* src = (i < 64) ? (piw2 + i * 128) : pib2;
    float acc = 0.f;
#pragma unroll 8
    for (int c = 0; c < 128; c++) acc += __ldg(src + c) * __ldg(W + c * 64 + j);
    (gsel ? g_Cg : g_Cm)[i * 64 + j] = acc;
}

// ---------------- K2: fused — part (blocks<npart), table (next 65), pre (rest) ----
// pre smem: piw1 0(256) pib1 256(64) Cm 320(4160) Cg 4480(4160) tot 8640
#define PRE_SMEM (8640 * 4)
__global__ void __launch_bounds__(128, 3) k_pre(
    const int* __restrict__ is_module,
    const float* __restrict__ pi_feat,
    const float* __restrict__ piw1, const float* __restrict__ pib1,
    const float* __restrict__ gw1, const float* __restrict__ gb1,
    const float* __restrict__ gw2, const float* __restrict__ gb2,
    const float* __restrict__ o_w1,
    const float* __restrict__ o_b2, float* __restrict__ out, int n, int npart)
{
    int b = blockIdx.x;
    if (b < npart) {
        // ---- partition nodes by type + zero per-node scalars (512 nodes/block)
        int base = b * 512;
#pragma unroll 1
        for (int it = 0; it < 4; it++) {
            int i = base + it * 128 + threadIdx.x;
            bool valid = i < n;
            if (valid) { g_pos[i] = 0.f; g_cntm[i] = 0.f; g_cntg[i] = 0.f; }
            bool m = valid && (is_module[i] == 1);
            bool g = valid && !m;
            unsigned bm = __ballot_sync(0xffffffffu, m);
            unsigned bg = __ballot_sync(0xffffffffu, g);
            int lane = threadIdx.x & 31;
            int base_m = 0, base_g = 0;
            if (lane == 0) {
                base_m = atomicAdd(&g_np[0], __popc(bm));
                base_g = atomicAdd(&g_np[1], __popc(bg));
            }
            base_m = __shfl_sync(0xffffffffu, base_m, 0);
            base_g = __shfl_sync(0xffffffffu, base_g, 0);
            unsigned lt = (1u << lane) - 1u;
            if (m) g_perm_m[base_m + __popc(bm & lt)] = i;
            if (g) g_perm_g[base_g + __popc(bg & lt)] = i;
        }
        return;
    }
    if (b < npart + 65) {
        // ---- piecewise-linear table (output used by k_out only)
        __shared__ float s_t[64], s_w[64], s_b[64];
        __shared__ int s_pos[64];
        __shared__ float s_a[128], s_c[128];
        int j = threadIdx.x;
        int s = b - npart;
        if (j < 64) {
            float w = gw1[j], bb = gb1[j];
            s_w[j] = w; s_b[j] = bb;
            s_t[j] = (w != 0.f) ? (-bb / w) : 3.0e38f;
        }
        __syncthreads();
        if (j < 64) {
            float t = s_t[j];
            int r = 0;
            for (int i = 0; i < 64; i++) {
                float ti = s_t[i];
                if (ti < t || (ti == t && i < j)) r++;
            }
            s_pos[j] = r;
        }
        __syncthreads();
        if (s == 0 && j < 64) g_knots[s_pos[j]] = s_t[j];
        {
            float a = 0.f, c = __ldg(gb2 + j);
#pragma unroll 8
            for (int k = 0; k < 64; k++) {
                float w = s_w[k], bb = s_b[k];
                bool positive = (w > 0.f) ? (s > s_pos[k])
                               : (w < 0.f) ? (s <= s_pos[k])
                               : (bb > 0.f);
                float sc = positive ? 1.0f : 0.1f;
                float gv = __ldg(gw2 + k * 128 + j);
                a += sc * w * gv;
                c += sc * bb * gv;
            }
            s_a[j] = a; s_c[j] = c;
        }
        __syncthreads();
        float A = 0.f, B = 0.f;
#pragma unroll 8
        for (int c = 0; c < 128; c++) {
            float o = __ldg(o_w1 + (size_t)(128 + c) * 128 + j);
            A += s_a[c] * o;
            B += s_c[c] * o;
        }
        g_A[s * 128 + j] = A;
        g_B[s * 128 + j] = B;
        return;
    }
    // ---- pre: hid_pi -> p_m, p_g; seed out
    extern __shared__ float sm[];
    {
        int t = threadIdx.x;
        for (int i = t; i < 256; i += 128) sm[i] = piw1[i];
        for (int i = t; i < 64; i += 128) sm[256 + i] = pib1[i];
        for (int i = t; i < 4160; i += 128) sm[320 + i] = g_Cm[i];
        for (int i = t; i < 4160; i += 128) sm[4480 + i] = g_Cg[i];
    }
    __syncthreads();

    int tile = b - npart - 65;
    int nd0 = tile * 256 + threadIdx.x;
    if (nd0 >= n) return;
    int nd1 = nd0 + 128;
    bool v1 = nd1 < n;
    int nd1c = v1 ? nd1 : nd0;

    float ob2 = __ldg(o_b2);
    out[nd0] = ob2;
    if (v1) out[nd1] = ob2;

    float4 pa = __ldg((const float4*)pi_feat + nd0);
    float4 pb = __ldg((const float4*)pi_feat + nd1c);

    u64 ha[32], hb[32];
    {
        const u64* bp = (const u64*)(sm + 256);
#pragma unroll
        for (int i = 0; i < 32; i++) { ha[i] = bp[i]; hb[i] = bp[i]; }
        l1in2(ha, hb, pa.x, pb.x, sm + 0 * 64);
        l1in2(ha, hb, pa.y, pb.y, sm + 1 * 64);
        l1in2(ha, hb, pa.z, pb.z, sm + 2 * 64);
        l1in2(ha, hb, pa.w, pb.w, sm + 3 * 64);
        leaky_pack(ha);
        leaky_pack(hb);
    }
    u64 aa[8], ab[8];
#pragma unroll 1
    for (int c = 0; c < 4; c++) {
        layer2_c16<64>(ha, hb, sm + 320, sm + 320 + 64 * 64, c * 16, aa, ab);
        u64* oa = (u64*)(g_pm + (size_t)nd0 * 64 + c * 16);
        u64* ob = (u64*)(g_pm + (size_t)nd1 * 64 + c * 16);
#pragma unroll
        for (int i = 0; i < 8; i++) oa[i] = aa[i];
        if (v1) {
#pragma unroll
            for (int i = 0; i < 8; i++) ob[i] = ab[i];
        }
    }
#pragma unroll 1
    for (int c = 0; c < 4; c++) {
        layer2_c16<64>(ha, hb, sm + 4480, sm + 4480 + 64 * 64, c * 16, aa, ab);
        u64* oa = (u64*)(g_pg + (size_t)nd0 * 64 + c * 16);
        u64* ob = (u64*)(g_pg + (size_t)nd1 * 64 + c * 16);
#pragma unroll
        for (int i = 0; i < 8; i++) oa[i] = aa[i];
        if (v1) {
#pragma unroll
            for (int i = 0; i < 8; i++) ob[i] = ab[i];
        }
    }
}

// ---------------- K3: edge gather + reduction, half-warp per edge, 64-dim ----------
#define EPHW 4
__global__ void __launch_bounds__(256) k_edges_all(
    const int* __restrict__ src_m, const int* __restrict__ dst_m,
    const int* __restrict__ src_g, const int* __restrict__ dst_g,
    const float* __restrict__ bitpos, int Em, int Eg)
{
    int l16 = threadIdx.x & 15;
    long long hw = ((long long)blockIdx.x * blockDim.x + threadIdx.x) >> 4;
    long long base = hw * EPHW;
    long long Etot = (long long)Em + Eg;
    if (base >= Etot) return;
    int cnt = (int)(Etot - base < EPHW ? Etot - base : EPHW);

    int s[EPHW], d[EPHW];
    bool ism[EPHW];
#pragma unroll
    for (int i = 0; i < EPHW; i++) {
        if (i < cnt) {
            long long e = base + i;
            if (e < Em) {
                ism[i] = true;
                s[i] = __ldg(src_m + e);
                d[i] = __ldg(dst_m + e);
            } else {
                ism[i] = false;
                s[i] = __ldg(src_g + (e - Em));
                d[i] = __ldg(dst_g + (e - Em));
            }
        }
    }
    float4 v[EPHW];
#pragma unroll
    for (int i = 0; i < EPHW; i++)
        if (i < cnt)
            v[i] = __ldg((const float4*)((ism[i] ? g_pm : g_pg) + (size_t)s[i] * 64) + l16);
#pragma unroll
    for (int i = 0; i < EPHW; i++) {
        if (i < cnt) {
            float* p = (ism[i] ? g_sum_m : g_sum_g) + (size_t)d[i] * 64 + l16 * 4;
            asm volatile("red.global.add.v4.f32 [%0], {%1,%2,%3,%4};"
                         :: "l"(p), "f"(v[i].x), "f"(v[i].y), "f"(v[i].z), "f"(v[i].w)
                         : "memory");
            if (l16 == 0) {
                if (ism[i]) {
                    atomicAdd(g_cntm + d[i], 1.0f);
                    atomicAdd(g_pos + d[i], __ldg(bitpos + base + i));
                } else {
                    atomicAdd(g_cntg + d[i], 1.0f);
                }
            }
        }
    }
}

// ---------------- K4: node MLP, single wave -> g_h ----------
// smem floats: w1f 0(4096) | w1pos 4096(64) | b1 4160(64) | w2 4224(8192) | b2 12416(128)
#define NODE_SMEM (12544 * 4)
__global__ void __launch_bounds__(128, 3) k_node_all(
    const float* __restrict__ feat, const int* __restrict__ is_po,
    const float* __restrict__ nm_w1, const float* __restrict__ nm_b1,
    const float* __restrict__ nm_w2, const float* __restrict__ nm_b2,
    const float* __restrict__ ng_w1, const float* __restrict__ ng_b1,
    const float* __restrict__ ng_w2, const float* __restrict__ ng_b2)
{
    int nbm = (g_np[0] + 255) >> 8;
    bool MOD = (int)blockIdx.x < nbm;
    int tile = MOD ? blockIdx.x : blockIdx.x - nbm;
    int total = MOD ? g_np[0] : g_np[1];
    if (tile * 256 >= total) return;

    const float* w1 = MOD ? nm_w1 : ng_w1;
    const float* b1 = MOD ? nm_b1 : ng_b1;
    const float* w2 = MOD ? nm_w2 : ng_w2;
    const float* b2 = MOD ? nm_b2 : ng_b2;
    const float* w1f = w1 + (MOD ? 129 : 128) * 64;
    const int* perm = MOD ? g_perm_m : g_perm_g;
    const float* sums = MOD ? g_sum_m : g_sum_g;
    const float* cnts = MOD ? g_cntm : g_cntg;

    extern __shared__ float sm[];
    float* s_w1f = sm;
    float* s_w1pos = sm + 4096;
    float* s_b1 = sm + 4160;
    float* s_w2 = sm + 4224;
    float* s_b2 = sm + 12416;
    {
        int t = threadIdx.x;
        for (int i = t; i < 4096; i += 128) s_w1f[i] = w1f[i];
        for (int i = t; i < 64; i += 128) s_w1pos[i] = MOD ? w1[128 * 64 + i] : 0.f;
        for (int i = t; i < 64; i += 128) s_b1[i] = b1[i];
        for (int i = t; i < 8192; i += 128) s_w2[i] = w2[i];
        for (int i = t; i < 128; i += 128) s_b2[i] = b2[i];
    }
    __syncthreads();

    int t0 = tile * 256 + threadIdx.x;
    if (t0 >= total) return;
    int t1 = t0 + 128;
    bool v1 = t1 < total;
    int nda = perm[t0];
    int ndb = v1 ? perm[t1] : nda;

    float inva = 1.0f / fmaxf(cnts[nda], 1.0f);
    float invb = 1.0f / fmaxf(cnts[ndb], 1.0f);
    const u64* sra = (const u64*)(sums + (size_t)nda * 64);
    const u64* srb = (const u64*)(sums + (size_t)ndb * 64);

    u64 ha[32], hb[32];
    {
        const u64* bp = (const u64*)s_b1;
        u64 iva = pack2(inva, inva), ivb = pack2(invb, invb);
#pragma unroll
        for (int i = 0; i < 32; i++) {
            u64 a = bp[i], b = bp[i];
            fma2(a, iva, __ldg(sra + i));
            fma2(b, ivb, __ldg(srb + i));
            ha[i] = a; hb[i] = b;
        }
    }
    if (MOD) {
        float posa = g_pos[nda] * inva;
        float posb = g_pos[ndb] * invb;
        l1in2(ha, hb, posa, posb, s_w1pos);
    }
    {
        const float4* fa = (const float4*)(feat + (size_t)nda * 64);
        const float4* fb = (const float4*)(feat + (size_t)ndb * 64);
#pragma unroll 2
        for (int k4 = 0; k4 < 16; k4++) {
            float4 va = __ldg(fa + k4);
            float4 vb = __ldg(fb + k4);
            const float* wr = s_w1f + (k4 * 4) * 64;
            l1in2(ha, hb, va.x, vb.x, wr);
            l1in2(ha, hb, va.y, vb.y, wr + 64);
            l1in2(ha, hb, va.z, vb.z, wr + 128);
            l1in2(ha, hb, va.w, vb.w, wr + 192);
        }
    }
    leaky_pack(ha);
    leaky_pack(hb);

    bool keepa = (__ldg(is_po + nda) != 1);
    bool keepb = (__ldg(is_po + ndb) != 1);
    float* ora = g_h + (size_t)nda * 128;
    float* orb = g_h + (size_t)ndb * 128;
    u64 aa[8], ab[8];
#pragma unroll 1
    for (int c = 0; c < 8; c++) {
        layer2_c16<128>(ha, hb, s_w2, s_b2, c * 16, aa, ab);
        u64* oa = (u64*)(ora + c * 16);
#pragma unroll
        for (int i = 0; i < 8; i++) {
            float x, y; unpack2(aa[i], x, y);
            if (keepa) { x = fmaxf(x, 0.f); y = fmaxf(y, 0.f); }
            oa[i] = pack2(x, y);
        }
        if (v1) {
            u64* ob = (u64*)(orb + c * 16);
#pragma unroll
            for (int i = 0; i < 8; i++) {
                float x, y; unpack2(ab[i], x, y);
                if (keepb) { x = fmaxf(x, 0.f); y = fmaxf(y, 0.f); }
                ob[i] = pack2(x, y);
            }
        }
    }
}

// ---------------- K5: readout, hidden-half split, 2 sub-tiles/block ----------------
// smem floats: w1h 0..8191 | A 8192 (65*66=4290) | B 12482 (4290) |
//              b1 16772(64) | w2 16836(64) | knots 16900(64) -> 16964 floats
#define SM_A 8192
#define SM_B 12482
#define SM_B1 16772
#define SM_W2 16836
#define SM_KN 16900
#define OUT_SMEM (16964 * 4)
__global__ void __launch_bounds__(128, 3) k_out(
    const float* __restrict__ o_w1, const float* __restrict__ o_b1,
    const float* __restrict__ o_w2, const float* __restrict__ level,
    float* __restrict__ out, int n)
{
    int half = blockIdx.x & 1;
    int pairid = blockIdx.x >> 1;   // 0..195

    extern __shared__ float sm[];
    for (int i = threadIdx.x; i < 8192; i += 128) {
        int row = i >> 6, col = i & 63;
        sm[i] = o_w1[row * 128 + half * 64 + col];
    }
    for (int i = threadIdx.x; i < 65 * 64; i += 128) {
        int seg = i >> 6, col = i & 63;
        sm[SM_A + seg * 66 + col] = g_A[seg * 128 + half * 64 + col];
        sm[SM_B + seg * 66 + col] = g_B[seg * 128 + half * 64 + col];
    }
    for (int i = threadIdx.x; i < 64; i += 128) {
        sm[SM_B1 + i] = o_b1[half * 64 + i];
        sm[SM_W2 + i] = o_w2[half * 64 + i];
        sm[SM_KN + i] = g_knots[i];
    }
    __syncthreads();

#pragma unroll 1
    for (int sub = 0; sub < 2; sub++) {
        int tile = pairid * 2 + sub;
        int nd0 = tile * 256 + threadIdx.x;
        if (nd0 >= n) break;
        int nd1 = nd0 + 128;
        bool v1 = nd1 < n;
        int nd1c = v1 ? nd1 : nd0;

        float lva = __ldg(level + nd0);
        float lvb = __ldg(level + nd1c);
        int sa = 0, sb = 0;
#pragma unroll
        for (int k = 0; k < 64; k++) {
            float kn = sm[SM_KN + k];
            sa += (kn < lva) ? 1 : 0;
            sb += (kn < lvb) ? 1 : 0;
        }

        u64 aa[32], ab[32];
        {
            const float* Aa = sm + SM_A + sa * 66;
            const float* Ba = sm + SM_B + sa * 66;
            const float* Ab = sm + SM_A + sb * 66;
            const float* Bb = sm + SM_B + sb * 66;
            const float* br = sm + SM_B1;
#pragma unroll
            for (int i = 0; i < 32; i++) {
                float a0 = fmaf(Aa[2 * i], lva, br[2 * i] + Ba[2 * i]);
                float a1 = fmaf(Aa[2 * i + 1], lva, br[2 * i + 1] + Ba[2 * i + 1]);
                aa[i] = pack2(a0, a1);
                float b0 = fmaf(Ab[2 * i], lvb, br[2 * i] + Bb[2 * i]);
                float b1 = fmaf(Ab[2 * i + 1], lvb, br[2 * i + 1] + Bb[2 * i + 1]);
                ab[i] = pack2(b0, b1);
            }
        }
        const float4* xa = (const float4*)(g_h + (size_t)nd0 * 128);
        const float4* xb = (const float4*)(g_h + (size_t)nd1c * 128);
#pragma unroll 2
        for (int k4 = 0; k4 < 32; k4++) {
            float4 va = __ldg(xa + k4);
            float4 vb = __ldg(xb + k4);
            const float* wr = sm + (k4 * 4) * 64;
            l1in2(aa, ab, va.x, vb.x, wr);
            l1in2(aa, ab, va.y, vb.y, wr + 64);
            l1in2(aa, ab, va.z, vb.z, wr + 128);
            l1in2(aa, ab, va.w, vb.w, wr + 192);
        }
        float ra = 0.f, rb = 0.f;
#pragma unroll
        for (int i = 0; i < 32; i++) {
            float x, y; unpack2(aa[i], x, y);
            ra += leaky(x) * sm[SM_W2 + 2 * i] + leaky(y) * sm[SM_W2 + 2 * i + 1];
            unpack2(ab[i], x, y);
            rb += leaky(x) * sm[SM_W2 + 2 * i] + leaky(y) * sm[SM_W2 + 2 * i + 1];
        }
        atomicAdd(out + nd0, ra);
        if (v1) atomicAdd(out + nd1, rb);
    }
}

// ---------------- host launch ----------------
extern "C" void kernel_launch(void* const* d_in, const int* in_sizes, int n_in,
                              void* d_out, int out_size)
{
    const float* feat    = (const float*)d_in[0];
    const float* pi_feat = (const float*)d_in[1];
    const float* level   = (const float*)d_in[2];
    const float* bitpos  = (const float*)d_in[3];

    const int *is_po, *is_module, *src_m, *dst_m, *src_g, *dst_g;
    const float *pi_w1, *pi_b1, *pi_w2, *pi_b2;
    const float *nm_w1, *nm_b1, *nm_w2, *nm_b2;
    const float *ng_w1, *ng_b1, *ng_w2, *ng_b2;
    const float *gw1, *gb1, *gw2, *gb2;
    const float *o_w1, *o_b1, *o_w2, *o_b2;
    int Em, Eg;

    if (in_sizes[4] < 1000) {
        // reference-signature order
        pi_w1 = (const float*)d_in[4];  pi_b1 = (const float*)d_in[5];
        pi_w2 = (const float*)d_in[6];  pi_b2 = (const float*)d_in[7];
        nm_w1 = (const float*)d_in[8];  nm_b1 = (const float*)d_in[9];
        nm_w2 = (const float*)d_in[10]; nm_b2 = (const float*)d_in[11];
        ng_w1 = (const float*)d_in[12]; ng_b1 = (const float*)d_in[13];
        ng_w2 = (const float*)d_in[14]; ng_b2 = (const float*)d_in[15];
        gw1 = (const float*)d_in[16];   gb1 = (const float*)d_in[17];
        gw2 = (const float*)d_in[18];   gb2 = (const float*)d_in[19];
        o_w1 = (const float*)d_in[20];  o_b1 = (const float*)d_in[21];
        o_w2 = (const float*)d_in[22];  o_b2 = (const float*)d_in[23];
        is_po = (const int*)d_in[24];   is_module = (const int*)d_in[25];
        src_m = (const int*)d_in[26];   dst_m = (const int*)d_in[27];
        src_g = (const int*)d_in[28];   dst_g = (const int*)d_in[29];
        Em = in_sizes[26]; Eg = in_sizes[28];
    } else {
        // setup_inputs dict order
        is_po = (const int*)d_in[4];    is_module = (const int*)d_in[5];
        src_m = (const int*)d_in[6];    dst_m = (const int*)d_in[7];
        src_g = (const int*)d_in[8];    dst_g = (const int*)d_in[9];
        pi_w1 = (const float*)d_in[10]; pi_b1 = (const float*)d_in[11];
        pi_w2 = (const float*)d_in[12]; pi_b2 = (const float*)d_in[13];
        nm_w1 = (const float*)d_in[14]; nm_b1 = (const float*)d_in[15];
        nm_w2 = (const float*)d_in[16]; nm_b2 = (const float*)d_in[17];
        ng_w1 = (const float*)d_in[18]; ng_b1 = (const float*)d_in[19];
        ng_w2 = (const float*)d_in[20]; ng_b2 = (const float*)d_in[21];
        gw1 = (const float*)d_in[22];   gb1 = (const float*)d_in[23];
        gw2 = (const float*)d_in[24];   gb2 = (const float*)d_in[25];
        o_w1 = (const float*)d_in[26];  o_b1 = (const float*)d_in[27];
        o_w2 = (const float*)d_in[28];  o_b2 = (const float*)d_in[29];
        Em = in_sizes[6]; Eg = in_sizes[8];
    }

    int n = in_sizes[2];  // level has N elements

    cudaFuncSetAttribute(k_pre, cudaFuncAttributeMaxDynamicSharedMemorySize, PRE_SMEM);
    cudaFuncSetAttribute(k_node_all, cudaFuncAttributeMaxDynamicSharedMemorySize, NODE_SMEM);
    cudaFuncSetAttribute(k_out, cudaFuncAttributeMaxDynamicSharedMemorySize, OUT_SMEM);

    int ntile = (n + 255) / 256;          // 256-node tiles
    int npart = (n + 511) / 512;          // part blocks (512 nodes each)

    void* p = nullptr;
    cudaGetSymbolAddress(&p, g_sum_m);
    cudaMemsetAsync(p, 0, (size_t)n * 64 * 4);
    cudaGetSymbolAddress(&p, g_sum_g);
    cudaMemsetAsync(p, 0, (size_t)n * 64 * 4);
    cudaGetSymbolAddress(&p, g_np);
    cudaMemsetAsync(p, 0, 8);

    k_compose<<<dim3(65, 2), 64>>>(pi_w2, pi_b2, nm_w1, ng_w1);

    k_pre<<<npart + 65 + ntile, 128, PRE_SMEM>>>(
        is_module, pi_feat, pi_w1, pi_b1,
        gw1, gb1, gw2, gb2, o_w1,
        o_b2, (float*)d_out, n, npart);

    long long Etot = (long long)Em + Eg;
    long long hws = (Etot + EPHW - 1) / EPHW;
    int eb = (int)((hws * 16 + 255) / 256);
    k_edges_all<<<eb, 256>>>(src_m, dst_m, src_g, dst_g, bitpos, Em, Eg);

    k_node_all<<<ntile + 1, 128, NODE_SMEM>>>(
        feat, is_po,
        nm_w1, nm_b1, nm_w2, nm_b2,
        ng_w1, ng_b1, ng_w2, ng_b2);

    k_out<<<((ntile + 1) / 2) * 2, 128, OUT_SMEM>>>(
        o_w1, o_b1, o_w2, level, (float*)d_out, n);
}

// round 9
// speedup vs baseline: 1.1074x; 1.1074x over previous
#include <cuda_runtime.h>

#define NN 100000

typedef unsigned long long u64;

// ---------------- scratch (device globals) ----------------
__device__ float g_pm[(size_t)NN * 64];
__device__ float g_pg[(size_t)NN * 64];
__device__ float g_sum_m[(size_t)NN * 64];
__device__ float g_sum_g[(size_t)NN * 64];
__device__ float g_pos[NN];
__device__ float g_cntm[NN];
__device__ float g_cntg[NN];
__device__ float g_h[(size_t)NN * 128];
__device__ int   g_np[2];          // [0]=nm, [1]=ng
__device__ int   g_perm_m[NN];
__device__ int   g_perm_g[NN];
__device__ float g_Cm[65 * 64];
__device__ float g_Cg[65 * 64];
__device__ float g_A[65 * 128];
__device__ float g_B[65 * 128];
__device__ float g_knots[64];

__device__ __forceinline__ float leaky(float x) { return x > 0.f ? x : 0.1f * x; }

// ---- packed f32x2 helpers ----
__device__ __forceinline__ u64 pack2(float x, float y) {
    u64 r; asm("mov.b64 %0,{%1,%2};" : "=l"(r) : "f"(x), "f"(y)); return r;
}
__device__ __forceinline__ void unpack2(u64 v, float& x, float& y) {
    asm("mov.b64 {%0,%1},%2;" : "=f"(x), "=f"(y) : "l"(v));
}
__device__ __forceinline__ void fma2(u64& acc, u64 a, u64 b) {
    asm("fma.rn.f32x2 %0,%1,%2,%0;" : "+l"(acc) : "l"(a), "l"(b));
}

// one input feature per node (2 nodes) into 64-wide accumulators (32 u64 each)
__device__ __forceinline__ void l1in2(u64* ha, u64* hb, float xa_, float xb_,
                                      const float* w) {
    u64 xa = pack2(xa_, xa_), xb = pack2(xb_, xb_);
    const ulonglong2* wp = (const ulonglong2*)w;
#pragma unroll
    for (int i = 0; i < 16; i++) {
        ulonglong2 ww = wp[i];
        fma2(ha[2 * i], xa, ww.x);
        fma2(ha[2 * i + 1], xa, ww.y);
        fma2(hb[2 * i], xb, ww.x);
        fma2(hb[2 * i + 1], xb, ww.y);
    }
}

// 64 hidden (activated, packed) x 2 nodes -> 32 outputs at column j0 of [64,STRIDE]
template <int STRIDE>
__device__ __forceinline__ void layer2_chunk2(
    const u64* ha, const u64* hb, const float* w2, const float* b2, int j0,
    u64* aa, u64* ab)
{
    const u64* bp = (const u64*)(b2 + j0);
#pragma unroll
    for (int i = 0; i < 16; i++) { aa[i] = bp[i]; ab[i] = bp[i]; }
#pragma unroll 4
    for (int kk = 0; kk < 32; kk++) {
        float a0, a1, b0, b1;
        unpack2(ha[kk], a0, a1);
        unpack2(hb[kk], b0, b1);
        u64 xa0 = pack2(a0, a0), xa1 = pack2(a1, a1);
        u64 xb0 = pack2(b0, b0), xb1 = pack2(b1, b1);
        const ulonglong2* w0 = (const ulonglong2*)(w2 + (size_t)(2 * kk) * STRIDE + j0);
        const ulonglong2* w1 = (const ulonglong2*)(w2 + (size_t)(2 * kk + 1) * STRIDE + j0);
#pragma unroll
        for (int i = 0; i < 8; i++) {
            ulonglong2 w = w0[i];
            fma2(aa[2 * i], xa0, w.x); fma2(aa[2 * i + 1], xa0, w.y);
            fma2(ab[2 * i], xb0, w.x); fma2(ab[2 * i + 1], xb0, w.y);
        }
#pragma unroll
        for (int i = 0; i < 8; i++) {
            ulonglong2 w = w1[i];
            fma2(aa[2 * i], xa1, w.x); fma2(aa[2 * i + 1], xa1, w.y);
            fma2(ab[2 * i], xb1, w.x); fma2(ab[2 * i + 1], xb1, w.y);
        }
    }
}

__device__ __forceinline__ void leaky_pack(u64* h2) {
#pragma unroll
    for (int i = 0; i < 32; i++) {
        float a, b; unpack2(h2[i], a, b);
        h2[i] = pack2(leaky(a), leaky(b));
    }
}

// ---------------- KC: composed projections Cm, Cg (tiny, must precede k_pre) ------
__global__ void k_compose(
    const float* __restrict__ piw2, const float* __restrict__ pib2,
    const float* __restrict__ nmw1, const float* __restrict__ ngw1)
{
    int i = blockIdx.x;       // 0..64
    int gsel = blockIdx.y;    // 0=m 1=g
    int j = threadIdx.x;      // 0..63
    const float* W = gsel ? ngw1 : nmw1;
    const float* src = (i < 64) ? (piw2 + i * 128) : pib2;
    float acc = 0.f;
#pragma unroll 8
    for (int c = 0; c < 128; c++) acc += __ldg(src + c) * __ldg(W + c * 64 + j);
    (gsel ? g_Cg : g_Cm)[i * 64 + j] = acc;
}

// ---------------- K2: fused — part (blocks<npart), table (next 65), pre (rest) ----
// pre smem: piw1 0(256) pib1 256(64) Cm 320(4160) Cg 4480(4160) tot 8640
#define PRE_SMEM (8640 * 4)
__global__ void __launch_bounds__(128) k_pre(
    const int* __restrict__ is_module,
    const float* __restrict__ pi_feat,
    const float* __restrict__ piw1, const float* __restrict__ pib1,
    const float* __restrict__ gw1, const float* __restrict__ gb1,
    const float* __restrict__ gw2, const float* __restrict__ gb2,
    const float* __restrict__ o_w1,
    const float* __restrict__ o_b2, float* __restrict__ out, int n, int npart)
{
    int b = blockIdx.x;
    if (b < npart) {
        // ---- partition nodes by type + zero per-node scalars (512 nodes/block)
        int base = b * 512;
#pragma unroll 1
        for (int it = 0; it < 4; it++) {
            int i = base + it * 128 + threadIdx.x;
            bool valid = i < n;
            if (valid) { g_pos[i] = 0.f; g_cntm[i] = 0.f; g_cntg[i] = 0.f; }
            bool m = valid && (is_module[i] == 1);
            bool g = valid && !m;
            unsigned bm = __ballot_sync(0xffffffffu, m);
            unsigned bg = __ballot_sync(0xffffffffu, g);
            int lane = threadIdx.x & 31;
            int base_m = 0, base_g = 0;
            if (lane == 0) {
                base_m = atomicAdd(&g_np[0], __popc(bm));
                base_g = atomicAdd(&g_np[1], __popc(bg));
            }
            base_m = __shfl_sync(0xffffffffu, base_m, 0);
            base_g = __shfl_sync(0xffffffffu, base_g, 0);
            unsigned lt = (1u << lane) - 1u;
            if (m) g_perm_m[base_m + __popc(bm & lt)] = i;
            if (g) g_perm_g[base_g + __popc(bg & lt)] = i;
        }
        return;
    }
    if (b < npart + 65) {
        // ---- piecewise-linear table (consumed by k_out only)
        __shared__ float s_t[64], s_w[64], s_b[64];
        __shared__ int s_pos[64];
        __shared__ float s_a[128], s_c[128];
        int j = threadIdx.x;
        int s = b - npart;
        if (j < 64) {
            float w = gw1[j], bb = gb1[j];
            s_w[j] = w; s_b[j] = bb;
            s_t[j] = (w != 0.f) ? (-bb / w) : 3.0e38f;
        }
        __syncthreads();
        if (j < 64) {
            float t = s_t[j];
            int r = 0;
            for (int i = 0; i < 64; i++) {
                float ti = s_t[i];
                if (ti < t || (ti == t && i < j)) r++;
            }
            s_pos[j] = r;
        }
        __syncthreads();
        if (s == 0 && j < 64) g_knots[s_pos[j]] = s_t[j];
        {
            float a = 0.f, c = __ldg(gb2 + j);
#pragma unroll 8
            for (int k = 0; k < 64; k++) {
                float w = s_w[k], bb = s_b[k];
                bool positive = (w > 0.f) ? (s > s_pos[k])
                               : (w < 0.f) ? (s <= s_pos[k])
                               : (bb > 0.f);
                float sc = positive ? 1.0f : 0.1f;
                float gv = __ldg(gw2 + k * 128 + j);
                a += sc * w * gv;
                c += sc * bb * gv;
            }
            s_a[j] = a; s_c[j] = c;
        }
        __syncthreads();
        float A = 0.f, B = 0.f;
#pragma unroll 8
        for (int c = 0; c < 128; c++) {
            float o = __ldg(o_w1 + (size_t)(128 + c) * 128 + j);
            A += s_a[c] * o;
            B += s_c[c] * o;
        }
        g_A[s * 128 + j] = A;
        g_B[s * 128 + j] = B;
        return;
    }
    // ---- pre: hid_pi -> p_m, p_g; seed out
    extern __shared__ float sm[];
    {
        int t = threadIdx.x;
        for (int i = t; i < 256; i += 128) sm[i] = piw1[i];
        for (int i = t; i < 64; i += 128) sm[256 + i] = pib1[i];
        for (int i = t; i < 4160; i += 128) sm[320 + i] = g_Cm[i];
        for (int i = t; i < 4160; i += 128) sm[4480 + i] = g_Cg[i];
    }
    __syncthreads();

    int tile = b - npart - 65;
    int nd0 = tile * 256 + threadIdx.x;
    if (nd0 >= n) return;
    int nd1 = nd0 + 128;
    bool v1 = nd1 < n;
    int nd1c = v1 ? nd1 : nd0;

    float ob2 = __ldg(o_b2);
    out[nd0] = ob2;
    if (v1) out[nd1] = ob2;

    float4 pa = __ldg((const float4*)pi_feat + nd0);
    float4 pb = __ldg((const float4*)pi_feat + nd1c);

    u64 ha[32], hb[32];
    {
        const u64* bp = (const u64*)(sm + 256);
#pragma unroll
        for (int i = 0; i < 32; i++) { ha[i] = bp[i]; hb[i] = bp[i]; }
        l1in2(ha, hb, pa.x, pb.x, sm + 0 * 64);
        l1in2(ha, hb, pa.y, pb.y, sm + 1 * 64);
        l1in2(ha, hb, pa.z, pb.z, sm + 2 * 64);
        l1in2(ha, hb, pa.w, pb.w, sm + 3 * 64);
        leaky_pack(ha);
        leaky_pack(hb);
    }
    u64 aa[16], ab[16];
#pragma unroll 1
    for (int c = 0; c < 2; c++) {
        layer2_chunk2<64>(ha, hb, sm + 320, sm + 320 + 64 * 64, c * 32, aa, ab);
        u64* oa = (u64*)(g_pm + (size_t)nd0 * 64 + c * 32);
        u64* ob = (u64*)(g_pm + (size_t)nd1 * 64 + c * 32);
#pragma unroll
        for (int i = 0; i < 16; i++) oa[i] = aa[i];
        if (v1) {
#pragma unroll
            for (int i = 0; i < 16; i++) ob[i] = ab[i];
        }
    }
#pragma unroll 1
    for (int c = 0; c < 2; c++) {
        layer2_chunk2<64>(ha, hb, sm + 4480, sm + 4480 + 64 * 64, c * 32, aa, ab);
        u64* oa = (u64*)(g_pg + (size_t)nd0 * 64 + c * 32);
        u64* ob = (u64*)(g_pg + (size_t)nd1 * 64 + c * 32);
#pragma unroll
        for (int i = 0; i < 16; i++) oa[i] = aa[i];
        if (v1) {
#pragma unroll
            for (int i = 0; i < 16; i++) ob[i] = ab[i];
        }
    }
}

// ---------------- K3: edge gather + reduction, half-warp per edge, 64-dim ----------
#define EPHW 4
__global__ void __launch_bounds__(256) k_edges_all(
    const int* __restrict__ src_m, const int* __restrict__ dst_m,
    const int* __restrict__ src_g, const int* __restrict__ dst_g,
    const float* __restrict__ bitpos, int Em, int Eg)
{
    int l16 = threadIdx.x & 15;
    long long hw = ((long long)blockIdx.x * blockDim.x + threadIdx.x) >> 4;
    long long base = hw * EPHW;
    long long Etot = (long long)Em + Eg;
    if (base >= Etot) return;
    int cnt = (int)(Etot - base < EPHW ? Etot - base : EPHW);

    int s[EPHW], d[EPHW];
    bool ism[EPHW];
#pragma unroll
    for (int i = 0; i < EPHW; i++) {
        if (i < cnt) {
            long long e = base + i;
            if (e < Em) {
                ism[i] = true;
                s[i] = __ldg(src_m + e);
                d[i] = __ldg(dst_m + e);
            } else {
                ism[i] = false;
                s[i] = __ldg(src_g + (e - Em));
                d[i] = __ldg(dst_g + (e - Em));
            }
        }
    }
    float4 v[EPHW];
#pragma unroll
    for (int i = 0; i < EPHW; i++)
        if (i < cnt)
            v[i] = __ldg((const float4*)((ism[i] ? g_pm : g_pg) + (size_t)s[i] * 64) + l16);
#pragma unroll
    for (int i = 0; i < EPHW; i++) {
        if (i < cnt) {
            float* p = (ism[i] ? g_sum_m : g_sum_g) + (size_t)d[i] * 64 + l16 * 4;
            asm volatile("red.global.add.v4.f32 [%0], {%1,%2,%3,%4};"
                         :: "l"(p), "f"(v[i].x), "f"(v[i].y), "f"(v[i].z), "f"(v[i].w)
                         : "memory");
            if (l16 == 0) {
                if (ism[i]) {
                    atomicAdd(g_cntm + d[i], 1.0f);
                    atomicAdd(g_pos + d[i], __ldg(bitpos + base + i));
                } else {
                    atomicAdd(g_cntg + d[i], 1.0f);
                }
            }
        }
    }
}

// ---------------- K4: node MLP (round-6 config) -> g_h ----------
// smem floats: w1f 0(4096) | w1pos 4096(64) | b1 4160(64) | w2 4224(8192) | b2 12416(128)
#define NODE_SMEM (12544 * 4)
__global__ void __launch_bounds__(128) k_node_all(
    const float* __restrict__ feat, const int* __restrict__ is_po,
    const float* __restrict__ nm_w1, const float* __restrict__ nm_b1,
    const float* __restrict__ nm_w2, const float* __restrict__ nm_b2,
    const float* __restrict__ ng_w1, const float* __restrict__ ng_b1,
    const float* __restrict__ ng_w2, const float* __restrict__ ng_b2)
{
    int nbm = (g_np[0] + 255) >> 8;
    bool MOD = (int)blockIdx.x < nbm;
    int tile = MOD ? blockIdx.x : blockIdx.x - nbm;
    int total = MOD ? g_np[0] : g_np[1];
    if (tile * 256 >= total) return;

    const float* w1 = MOD ? nm_w1 : ng_w1;
    const float* b1 = MOD ? nm_b1 : ng_b1;
    const float* w2 = MOD ? nm_w2 : ng_w2;
    const float* b2 = MOD ? nm_b2 : ng_b2;
    const float* w1f = w1 + (MOD ? 129 : 128) * 64;
    const int* perm = MOD ? g_perm_m : g_perm_g;
    const float* sums = MOD ? g_sum_m : g_sum_g;
    const float* cnts = MOD ? g_cntm : g_cntg;

    extern __shared__ float sm[];
    float* s_w1f = sm;
    float* s_w1pos = sm + 4096;
    float* s_b1 = sm + 4160;
    float* s_w2 = sm + 4224;
    float* s_b2 = sm + 12416;
    {
        int t = threadIdx.x;
        for (int i = t; i < 4096; i += 128) s_w1f[i] = w1f[i];
        for (int i = t; i < 64; i += 128) s_w1pos[i] = MOD ? w1[128 * 64 + i] : 0.f;
        for (int i = t; i < 64; i += 128) s_b1[i] = b1[i];
        for (int i = t; i < 8192; i += 128) s_w2[i] = w2[i];
        for (int i = t; i < 128; i += 128) s_b2[i] = b2[i];
    }
    __syncthreads();

    int t0 = tile * 256 + threadIdx.x;
    if (t0 >= total) return;
    int t1 = t0 + 128;
    bool v1 = t1 < total;
    int nda = perm[t0];
    int ndb = v1 ? perm[t1] : nda;

    float inva = 1.0f / fmaxf(cnts[nda], 1.0f);
    float invb = 1.0f / fmaxf(cnts[ndb], 1.0f);
    const u64* sra = (const u64*)(sums + (size_t)nda * 64);
    const u64* srb = (const u64*)(sums + (size_t)ndb * 64);

    u64 ha[32], hb[32];
    {
        const u64* bp = (const u64*)s_b1;
        u64 iva = pack2(inva, inva), ivb = pack2(invb, invb);
#pragma unroll
        for (int i = 0; i < 32; i++) {
            u64 a = bp[i], b = bp[i];
            fma2(a, iva, __ldg(sra + i));
            fma2(b, ivb, __ldg(srb + i));
            ha[i] = a; hb[i] = b;
        }
    }
    if (MOD) {
        float posa = g_pos[nda] * inva;
        float posb = g_pos[ndb] * invb;
        l1in2(ha, hb, posa, posb, s_w1pos);
    }
    {
        const float4* fa = (const float4*)(feat + (size_t)nda * 64);
        const float4* fb = (const float4*)(feat + (size_t)ndb * 64);
#pragma unroll 2
        for (int k4 = 0; k4 < 16; k4++) {
            float4 va = __ldg(fa + k4);
            float4 vb = __ldg(fb + k4);
            const float* wr = s_w1f + (k4 * 4) * 64;
            l1in2(ha, hb, va.x, vb.x, wr);
            l1in2(ha, hb, va.y, vb.y, wr + 64);
            l1in2(ha, hb, va.z, vb.z, wr + 128);
            l1in2(ha, hb, va.w, vb.w, wr + 192);
        }
    }
    leaky_pack(ha);
    leaky_pack(hb);

    bool keepa = (__ldg(is_po + nda) != 1);
    bool keepb = (__ldg(is_po + ndb) != 1);
    float* ora = g_h + (size_t)nda * 128;
    float* orb = g_h + (size_t)ndb * 128;
    u64 aa[16], ab[16];
#pragma unroll 1
    for (int c = 0; c < 4; c++) {
        layer2_chunk2<128>(ha, hb, s_w2, s_b2, c * 32, aa, ab);
        u64* oa = (u64*)(ora + c * 32);
#pragma unroll
        for (int i = 0; i < 16; i++) {
            float x, y; unpack2(aa[i], x, y);
            if (keepa) { x = fmaxf(x, 0.f); y = fmaxf(y, 0.f); }
            oa[i] = pack2(x, y);
        }
        if (v1) {
            u64* ob = (u64*)(orb + c * 32);
#pragma unroll
            for (int i = 0; i < 16; i++) {
                float x, y; unpack2(ab[i], x, y);
                if (keepb) { x = fmaxf(x, 0.f); y = fmaxf(y, 0.f); }
                ob[i] = pack2(x, y);
            }
        }
    }
}

// ---------------- K5: readout, hidden-half split (round-6 config) ----------------
// smem floats: w1h 0..8191 | A 8192 (65*66=4290) | B 12482 (4290) |
//              b1 16772(64) | w2 16836(64) | knots 16900(64) -> 16964 floats
#define SM_A 8192
#define SM_B 12482
#define SM_B1 16772
#define SM_W2 16836
#define SM_KN 16900
#define OUT_SMEM (16964 * 4)
__global__ void __launch_bounds__(128) k_out(
    const float* __restrict__ o_w1, const float* __restrict__ o_b1,
    const float* __restrict__ o_w2, const float* __restrict__ level,
    float* __restrict__ out, int n)
{
    int half = blockIdx.x & 1;
    int nb = blockIdx.x >> 1;

    extern __shared__ float sm[];
    for (int i = threadIdx.x; i < 8192; i += 128) {
        int row = i >> 6, col = i & 63;
        sm[i] = o_w1[row * 128 + half * 64 + col];
    }
    for (int i = threadIdx.x; i < 65 * 64; i += 128) {
        int seg = i >> 6, col = i & 63;
        sm[SM_A + seg * 66 + col] = g_A[seg * 128 + half * 64 + col];
        sm[SM_B + seg * 66 + col] = g_B[seg * 128 + half * 64 + col];
    }
    for (int i = threadIdx.x; i < 64; i += 128) {
        sm[SM_B1 + i] = o_b1[half * 64 + i];
        sm[SM_W2 + i] = o_w2[half * 64 + i];
        sm[SM_KN + i] = g_knots[i];
    }
    __syncthreads();

    int nd0 = nb * 256 + threadIdx.x;
    if (nd0 >= n) return;
    int nd1 = nd0 + 128;
    bool v1 = nd1 < n;
    int nd1c = v1 ? nd1 : nd0;

    float lva = __ldg(level + nd0);
    float lvb = __ldg(level + nd1c);
    int sa = 0, sb = 0;
#pragma unroll
    for (int k = 0; k < 64; k++) {
        float kn = sm[SM_KN + k];
        sa += (kn < lva) ? 1 : 0;
        sb += (kn < lvb) ? 1 : 0;
    }

    u64 aa[32], ab[32];
    {
        const float* Aa = sm + SM_A + sa * 66;
        const float* Ba = sm + SM_B + sa * 66;
        const float* Ab = sm + SM_A + sb * 66;
        const float* Bb = sm + SM_B + sb * 66;
        const float* br = sm + SM_B1;
#pragma unroll
        for (int i = 0; i < 32; i++) {
            float a0 = fmaf(Aa[2 * i], lva, br[2 * i] + Ba[2 * i]);
            float a1 = fmaf(Aa[2 * i + 1], lva, br[2 * i + 1] + Ba[2 * i + 1]);
            aa[i] = pack2(a0, a1);
            float b0 = fmaf(Ab[2 * i], lvb, br[2 * i] + Bb[2 * i]);
            float b1 = fmaf(Ab[2 * i + 1], lvb, br[2 * i + 1] + Bb[2 * i + 1]);
            ab[i] = pack2(b0, b1);
        }
    }
    const float4* xa = (const float4*)(g_h + (size_t)nd0 * 128);
    const float4* xb = (const float4*)(g_h + (size_t)nd1c * 128);
#pragma unroll 2
    for (int k4 = 0; k4 < 32; k4++) {
        float4 va = __ldg(xa + k4);
        float4 vb = __ldg(xb + k4);
        const float* wr = sm + (k4 * 4) * 64;
        l1in2(aa, ab, va.x, vb.x, wr);
        l1in2(aa, ab, va.y, vb.y, wr + 64);
        l1in2(aa, ab, va.z, vb.z, wr + 128);
        l1in2(aa, ab, va.w, vb.w, wr + 192);
    }
    float ra = 0.f, rb = 0.f;
#pragma unroll
    for (int i = 0; i < 32; i++) {
        float x, y; unpack2(aa[i], x, y);
        ra += leaky(x) * sm[SM_W2 + 2 * i] + leaky(y) * sm[SM_W2 + 2 * i + 1];
        unpack2(ab[i], x, y);
        rb += leaky(x) * sm[SM_W2 + 2 * i] + leaky(y) * sm[SM_W2 + 2 * i + 1];
    }
    atomicAdd(out + nd0, ra);
    if (v1) atomicAdd(out + nd1, rb);
}

// ---------------- host launch ----------------
extern "C" void kernel_launch(void* const* d_in, const int* in_sizes, int n_in,
                              void* d_out, int out_size)
{
    const float* feat    = (const float*)d_in[0];
    const float* pi_feat = (const float*)d_in[1];
    const float* level   = (const float*)d_in[2];
    const float* bitpos  = (const float*)d_in[3];

    const int *is_po, *is_module, *src_m, *dst_m, *src_g, *dst_g;
    const float *pi_w1, *pi_b1, *pi_w2, *pi_b2;
    const float *nm_w1, *nm_b1, *nm_w2, *nm_b2;
    const float *ng_w1, *ng_b1, *ng_w2, *ng_b2;
    const float *gw1, *gb1, *gw2, *gb2;
    const float *o_w1, *o_b1, *o_w2, *o_b2;
    int Em, Eg;

    if (in_sizes[4] < 1000) {
        // reference-signature order
        pi_w1 = (const float*)d_in[4];  pi_b1 = (const float*)d_in[5];
        pi_w2 = (const float*)d_in[6];  pi_b2 = (const float*)d_in[7];
        nm_w1 = (const float*)d_in[8];  nm_b1 = (const float*)d_in[9];
        nm_w2 = (const float*)d_in[10]; nm_b2 = (const float*)d_in[11];
        ng_w1 = (const float*)d_in[12]; ng_b1 = (const float*)d_in[13];
        ng_w2 = (const float*)d_in[14]; ng_b2 = (const float*)d_in[15];
        gw1 = (const float*)d_in[16];   gb1 = (const float*)d_in[17];
        gw2 = (const float*)d_in[18];   gb2 = (const float*)d_in[19];
        o_w1 = (const float*)d_in[20];  o_b1 = (const float*)d_in[21];
        o_w2 = (const float*)d_in[22];  o_b2 = (const float*)d_in[23];
        is_po = (const int*)d_in[24];   is_module = (const int*)d_in[25];
        src_m = (const int*)d_in[26];   dst_m = (const int*)d_in[27];
        src_g = (const int*)d_in[28];   dst_g = (const int*)d_in[29];
        Em = in_sizes[26]; Eg = in_sizes[28];
    } else {
        // setup_inputs dict order
        is_po = (const int*)d_in[4];    is_module = (const int*)d_in[5];
        src_m = (const int*)d_in[6];    dst_m = (const int*)d_in[7];
        src_g = (const int*)d_in[8];    dst_g = (const int*)d_in[9];
        pi_w1 = (const float*)d_in[10]; pi_b1 = (const float*)d_in[11];
        pi_w2 = (const float*)d_in[12]; pi_b2 = (const float*)d_in[13];
        nm_w1 = (const float*)d_in[14]; nm_b1 = (const float*)d_in[15];
        nm_w2 = (const float*)d_in[16]; nm_b2 = (const float*)d_in[17];
        ng_w1 = (const float*)d_in[18]; ng_b1 = (const float*)d_in[19];
        ng_w2 = (const float*)d_in[20]; ng_b2 = (const float*)d_in[21];
        gw1 = (const float*)d_in[22];   gb1 = (const float*)d_in[23];
        gw2 = (const float*)d_in[24];   gb2 = (const float*)d_in[25];
        o_w1 = (const float*)d_in[26];  o_b1 = (const float*)d_in[27];
        o_w2 = (const float*)d_in[28];  o_b2 = (const float*)d_in[29];
        Em = in_sizes[6]; Eg = in_sizes[8];
    }

    int n = in_sizes[2];  // level has N elements

    cudaFuncSetAttribute(k_pre, cudaFuncAttributeMaxDynamicSharedMemorySize, PRE_SMEM);
    cudaFuncSetAttribute(k_node_all, cudaFuncAttributeMaxDynamicSharedMemorySize, NODE_SMEM);
    cudaFuncSetAttribute(k_out, cudaFuncAttributeMaxDynamicSharedMemorySize, OUT_SMEM);

    int ntile = (n + 255) / 256;          // 256-node tiles
    int npart = (n + 511) / 512;          // part blocks (512 nodes each)

    void* p = nullptr;
    cudaGetSymbolAddress(&p, g_sum_m);
    cudaMemsetAsync(p, 0, (size_t)n * 64 * 4);
    cudaGetSymbolAddress(&p, g_sum_g);
    cudaMemsetAsync(p, 0, (size_t)n * 64 * 4);
    cudaGetSymbolAddress(&p, g_np);
    cudaMemsetAsync(p, 0, 8);

    k_compose<<<dim3(65, 2), 64>>>(pi_w2, pi_b2, nm_w1, ng_w1);

    k_pre<<<npart + 65 + ntile, 128, PRE_SMEM>>>(
        is_module, pi_feat, pi_w1, pi_b1,
        gw1, gb1, gw2, gb2, o_w1,
        o_b2, (float*)d_out, n, npart);

    long long Etot = (long long)Em + Eg;
    long long hws = (Etot + EPHW - 1) / EPHW;
    int eb = (int)((hws * 16 + 255) / 256);
    k_edges_all<<<eb, 256>>>(src_m, dst_m, src_g, dst_g, bitpos, Em, Eg);

    k_node_all<<<ntile + 1, 128, NODE_SMEM>>>(
        feat, is_po,
        nm_w1, nm_b1, nm_w2, nm_b2,
        ng_w1, ng_b1, ng_w2, ng_b2);

    k_out<<<ntile * 2, 128, OUT_SMEM>>>(
        o_w1, o_b1, o_w2, level, (float*)d_out, n);
}

// round 10
// speedup vs baseline: 1.1496x; 1.0382x over previous
#include <cuda_runtime.h>

#define NN 100000

typedef unsigned long long u64;

// ---------------- scratch (device globals) ----------------
__device__ float g_pm[(size_t)NN * 64];
__device__ float g_pg[(size_t)NN * 64];
__device__ float g_sum_m[(size_t)NN * 64];
__device__ float g_sum_g[(size_t)NN * 64];
__device__ float g_hidf_m[(size_t)NN * 64];   // b1 + feat@w1f for module nodes (perm order)
__device__ float g_hidf_g[(size_t)NN * 64];   // same for gate nodes (perm order)
__device__ float g_pos[NN];
__device__ float g_cntm[NN];
__device__ float g_cntg[NN];
__device__ float g_h[(size_t)NN * 128];
__device__ int   g_np[2];          // [0]=nm, [1]=ng
__device__ int   g_perm_m[NN];
__device__ int   g_perm_g[NN];
__device__ float g_Cm[65 * 64];
__device__ float g_Cg[65 * 64];
__device__ float g_A[65 * 128];
__device__ float g_B[65 * 128];
__device__ float g_knots[64];

__device__ __forceinline__ float leaky(float x) { return x > 0.f ? x : 0.1f * x; }

// ---- packed f32x2 helpers ----
__device__ __forceinline__ u64 pack2(float x, float y) {
    u64 r; asm("mov.b64 %0,{%1,%2};" : "=l"(r) : "f"(x), "f"(y)); return r;
}
__device__ __forceinline__ void unpack2(u64 v, float& x, float& y) {
    asm("mov.b64 {%0,%1},%2;" : "=f"(x), "=f"(y) : "l"(v));
}
__device__ __forceinline__ void fma2(u64& acc, u64 a, u64 b) {
    asm("fma.rn.f32x2 %0,%1,%2,%0;" : "+l"(acc) : "l"(a), "l"(b));
}

// one input feature per node (2 nodes) into 64-wide accumulators (32 u64 each)
__device__ __forceinline__ void l1in2(u64* ha, u64* hb, float xa_, float xb_,
                                      const float* w) {
    u64 xa = pack2(xa_, xa_), xb = pack2(xb_, xb_);
    const ulonglong2* wp = (const ulonglong2*)w;
#pragma unroll
    for (int i = 0; i < 16; i++) {
        ulonglong2 ww = wp[i];
        fma2(ha[2 * i], xa, ww.x);
        fma2(ha[2 * i + 1], xa, ww.y);
        fma2(hb[2 * i], xb, ww.x);
        fma2(hb[2 * i + 1], xb, ww.y);
    }
}

// 64 hidden (activated, packed) x 2 nodes -> 32 outputs at column j0 of [64,STRIDE]
template <int STRIDE>
__device__ __forceinline__ void layer2_chunk2(
    const u64* ha, const u64* hb, const float* w2, const float* b2, int j0,
    u64* aa, u64* ab)
{
    const u64* bp = (const u64*)(b2 + j0);
#pragma unroll
    for (int i = 0; i < 16; i++) { aa[i] = bp[i]; ab[i] = bp[i]; }
#pragma unroll 4
    for (int kk = 0; kk < 32; kk++) {
        float a0, a1, b0, b1;
        unpack2(ha[kk], a0, a1);
        unpack2(hb[kk], b0, b1);
        u64 xa0 = pack2(a0, a0), xa1 = pack2(a1, a1);
        u64 xb0 = pack2(b0, b0), xb1 = pack2(b1, b1);
        const ulonglong2* w0 = (const ulonglong2*)(w2 + (size_t)(2 * kk) * STRIDE + j0);
        const ulonglong2* w1 = (const ulonglong2*)(w2 + (size_t)(2 * kk + 1) * STRIDE + j0);
#pragma unroll
        for (int i = 0; i < 8; i++) {
            ulonglong2 w = w0[i];
            fma2(aa[2 * i], xa0, w.x); fma2(aa[2 * i + 1], xa0, w.y);
            fma2(ab[2 * i], xb0, w.x); fma2(ab[2 * i + 1], xb0, w.y);
        }
#pragma unroll
        for (int i = 0; i < 8; i++) {
            ulonglong2 w = w1[i];
            fma2(aa[2 * i], xa1, w.x); fma2(aa[2 * i + 1], xa1, w.y);
            fma2(ab[2 * i], xb1, w.x); fma2(ab[2 * i + 1], xb1, w.y);
        }
    }
}

__device__ __forceinline__ void leaky_pack(u64* h2) {
#pragma unroll
    for (int i = 0; i < 32; i++) {
        float a, b; unpack2(h2[i], a, b);
        h2[i] = pack2(leaky(a), leaky(b));
    }
}

// ---------------- KC: composed projections Cm, Cg (tiny, must precede k_pre) ------
__global__ void k_compose(
    const float* __restrict__ piw2, const float* __restrict__ pib2,
    const float* __restrict__ nmw1, const float* __restrict__ ngw1)
{
    int i = blockIdx.x;       // 0..64
    int gsel = blockIdx.y;    // 0=m 1=g
    int j = threadIdx.x;      // 0..63
    const float* W = gsel ? ngw1 : nmw1;
    const float* src = (i < 64) ? (piw2 + i * 128) : pib2;
    float acc = 0.f;
#pragma unroll 8
    for (int c = 0; c < 128; c++) acc += __ldg(src + c) * __ldg(W + c * 64 + j);
    (gsel ? g_Cg : g_Cm)[i * 64 + j] = acc;
}

// ---------------- KP: partition nodes by type + zero per-node scalars (side stream)
__global__ void k_part(const int* __restrict__ is_module, int n) {
    int i = blockIdx.x * blockDim.x + threadIdx.x;
    bool valid = i < n;
    if (valid) { g_pos[i] = 0.f; g_cntm[i] = 0.f; g_cntg[i] = 0.f; }
    bool m = valid && (is_module[i] == 1);
    bool g = valid && !m;
    unsigned bm = __ballot_sync(0xffffffffu, m);
    unsigned bg = __ballot_sync(0xffffffffu, g);
    int lane = threadIdx.x & 31;
    int base_m = 0, base_g = 0;
    if (lane == 0) {
        base_m = atomicAdd(&g_np[0], __popc(bm));
        base_g = atomicAdd(&g_np[1], __popc(bg));
    }
    base_m = __shfl_sync(0xffffffffu, base_m, 0);
    base_g = __shfl_sync(0xffffffffu, base_g, 0);
    unsigned lt = (1u << lane) - 1u;
    if (m) g_perm_m[base_m + __popc(bm & lt)] = i;
    if (g) g_perm_g[base_g + __popc(bg & lt)] = i;
}

// ---------------- KF: hidf = b1_sel + feat@w1f_sel (perm order; side stream) ------
// smem: w1f 4096 | b1 64
#define FEAT_SMEM ((4096 + 64) * 4)
__global__ void __launch_bounds__(128) k_feat(
    const float* __restrict__ feat,
    const float* __restrict__ nm_w1, const float* __restrict__ nm_b1,
    const float* __restrict__ ng_w1, const float* __restrict__ ng_b1)
{
    int nbm = (g_np[0] + 255) >> 8;
    bool MOD = (int)blockIdx.x < nbm;
    int tile = MOD ? blockIdx.x : blockIdx.x - nbm;
    int total = MOD ? g_np[0] : g_np[1];
    if (tile * 256 >= total) return;

    const float* w1 = MOD ? nm_w1 : ng_w1;
    const float* b1 = MOD ? nm_b1 : ng_b1;
    const float* w1f = w1 + (MOD ? 129 : 128) * 64;
    const int* perm = MOD ? g_perm_m : g_perm_g;
    float* outb = MOD ? g_hidf_m : g_hidf_g;

    extern __shared__ float sm[];
    for (int i = threadIdx.x; i < 4096; i += 128) sm[i] = w1f[i];
    for (int i = threadIdx.x; i < 64; i += 128) sm[4096 + i] = b1[i];
    __syncthreads();

    int t0 = tile * 256 + threadIdx.x;
    if (t0 >= total) return;
    int t1 = t0 + 128;
    bool v1 = t1 < total;
    int nda = perm[t0];
    int ndb = v1 ? perm[t1] : nda;

    u64 ha[32], hb[32];
    {
        const u64* bp = (const u64*)(sm + 4096);
#pragma unroll
        for (int i = 0; i < 32; i++) { ha[i] = bp[i]; hb[i] = bp[i]; }
    }
    {
        const float4* fa = (const float4*)(feat + (size_t)nda * 64);
        const float4* fb = (const float4*)(feat + (size_t)ndb * 64);
#pragma unroll 2
        for (int k4 = 0; k4 < 16; k4++) {
            float4 va = __ldg(fa + k4);
            float4 vb = __ldg(fb + k4);
            const float* wr = sm + (k4 * 4) * 64;
            l1in2(ha, hb, va.x, vb.x, wr);
            l1in2(ha, hb, va.y, vb.y, wr + 64);
            l1in2(ha, hb, va.z, vb.z, wr + 128);
            l1in2(ha, hb, va.w, vb.w, wr + 192);
        }
    }
    u64* oa = (u64*)(outb + (size_t)t0 * 64);
#pragma unroll
    for (int i = 0; i < 32; i++) oa[i] = ha[i];
    if (v1) {
        u64* ob = (u64*)(outb + (size_t)t1 * 64);
#pragma unroll
        for (int i = 0; i < 32; i++) ob[i] = hb[i];
    }
}

// ---------------- K2: fused — table (blocks<65), pre (rest) ----
// pre smem: piw1 0(256) pib1 256(64) Cm 320(4160) Cg 4480(4160) tot 8640
#define PRE_SMEM (8640 * 4)
__global__ void __launch_bounds__(128) k_pre(
    const float* __restrict__ pi_feat,
    const float* __restrict__ piw1, const float* __restrict__ pib1,
    const float* __restrict__ gw1, const float* __restrict__ gb1,
    const float* __restrict__ gw2, const float* __restrict__ gb2,
    const float* __restrict__ o_w1,
    const float* __restrict__ o_b2, float* __restrict__ out, int n)
{
    int b = blockIdx.x;
    if (b < 65) {
        // ---- piecewise-linear table (consumed by k_out only)
        __shared__ float s_t[64], s_w[64], s_b[64];
        __shared__ int s_pos[64];
        __shared__ float s_a[128], s_c[128];
        int j = threadIdx.x;
        int s = b;
        if (j < 64) {
            float w = gw1[j], bb = gb1[j];
            s_w[j] = w; s_b[j] = bb;
            s_t[j] = (w != 0.f) ? (-bb / w) : 3.0e38f;
        }
        __syncthreads();
        if (j < 64) {
            float t = s_t[j];
            int r = 0;
            for (int i = 0; i < 64; i++) {
                float ti = s_t[i];
                if (ti < t || (ti == t && i < j)) r++;
            }
            s_pos[j] = r;
        }
        __syncthreads();
        if (s == 0 && j < 64) g_knots[s_pos[j]] = s_t[j];
        {
            float a = 0.f, c = __ldg(gb2 + j);
#pragma unroll 8
            for (int k = 0; k < 64; k++) {
                float w = s_w[k], bb = s_b[k];
                bool positive = (w > 0.f) ? (s > s_pos[k])
                               : (w < 0.f) ? (s <= s_pos[k])
                               : (bb > 0.f);
                float sc = positive ? 1.0f : 0.1f;
                float gv = __ldg(gw2 + k * 128 + j);
                a += sc * w * gv;
                c += sc * bb * gv;
            }
            s_a[j] = a; s_c[j] = c;
        }
        __syncthreads();
        float A = 0.f, B = 0.f;
#pragma unroll 8
        for (int c = 0; c < 128; c++) {
            float o = __ldg(o_w1 + (size_t)(128 + c) * 128 + j);
            A += s_a[c] * o;
            B += s_c[c] * o;
        }
        g_A[s * 128 + j] = A;
        g_B[s * 128 + j] = B;
        return;
    }
    // ---- pre: hid_pi -> p_m, p_g; seed out
    extern __shared__ float sm[];
    {
        int t = threadIdx.x;
        for (int i = t; i < 256; i += 128) sm[i] = piw1[i];
        for (int i = t; i < 64; i += 128) sm[256 + i] = pib1[i];
        for (int i = t; i < 4160; i += 128) sm[320 + i] = g_Cm[i];
        for (int i = t; i < 4160; i += 128) sm[4480 + i] = g_Cg[i];
    }
    __syncthreads();

    int tile = b - 65;
    int nd0 = tile * 256 + threadIdx.x;
    if (nd0 >= n) return;
    int nd1 = nd0 + 128;
    bool v1 = nd1 < n;
    int nd1c = v1 ? nd1 : nd0;

    float ob2 = __ldg(o_b2);
    out[nd0] = ob2;
    if (v1) out[nd1] = ob2;

    float4 pa = __ldg((const float4*)pi_feat + nd0);
    float4 pb = __ldg((const float4*)pi_feat + nd1c);

    u64 ha[32], hb[32];
    {
        const u64* bp = (const u64*)(sm + 256);
#pragma unroll
        for (int i = 0; i < 32; i++) { ha[i] = bp[i]; hb[i] = bp[i]; }
        l1in2(ha, hb, pa.x, pb.x, sm + 0 * 64);
        l1in2(ha, hb, pa.y, pb.y, sm + 1 * 64);
        l1in2(ha, hb, pa.z, pb.z, sm + 2 * 64);
        l1in2(ha, hb, pa.w, pb.w, sm + 3 * 64);
        leaky_pack(ha);
        leaky_pack(hb);
    }
    u64 aa[16], ab[16];
#pragma unroll 1
    for (int c = 0; c < 2; c++) {
        layer2_chunk2<64>(ha, hb, sm + 320, sm + 320 + 64 * 64, c * 32, aa, ab);
        u64* oa = (u64*)(g_pm + (size_t)nd0 * 64 + c * 32);
        u64* ob = (u64*)(g_pm + (size_t)nd1 * 64 + c * 32);
#pragma unroll
        for (int i = 0; i < 16; i++) oa[i] = aa[i];
        if (v1) {
#pragma unroll
            for (int i = 0; i < 16; i++) ob[i] = ab[i];
        }
    }
#pragma unroll 1
    for (int c = 0; c < 2; c++) {
        layer2_chunk2<64>(ha, hb, sm + 4480, sm + 4480 + 64 * 64, c * 32, aa, ab);
        u64* oa = (u64*)(g_pg + (size_t)nd0 * 64 + c * 32);
        u64* ob = (u64*)(g_pg + (size_t)nd1 * 64 + c * 32);
#pragma unroll
        for (int i = 0; i < 16; i++) oa[i] = aa[i];
        if (v1) {
#pragma unroll
            for (int i = 0; i < 16; i++) ob[i] = ab[i];
        }
    }
}

// ---------------- K3: edge gather + reduction, half-warp per edge, 64-dim ----------
#define EPHW 4
__global__ void __launch_bounds__(256) k_edges_all(
    const int* __restrict__ src_m, const int* __restrict__ dst_m,
    const int* __restrict__ src_g, const int* __restrict__ dst_g,
    const float* __restrict__ bitpos, int Em, int Eg)
{
    int l16 = threadIdx.x & 15;
    long long hw = ((long long)blockIdx.x * blockDim.x + threadIdx.x) >> 4;
    long long base = hw * EPHW;
    long long Etot = (long long)Em + Eg;
    if (base >= Etot) return;
    int cnt = (int)(Etot - base < EPHW ? Etot - base : EPHW);

    int s[EPHW], d[EPHW];
    bool ism[EPHW];
#pragma unroll
    for (int i = 0; i < EPHW; i++) {
        if (i < cnt) {
            long long e = base + i;
            if (e < Em) {
                ism[i] = true;
                s[i] = __ldg(src_m + e);
                d[i] = __ldg(dst_m + e);
            } else {
                ism[i] = false;
                s[i] = __ldg(src_g + (e - Em));
                d[i] = __ldg(dst_g + (e - Em));
            }
        }
    }
    float4 v[EPHW];
#pragma unroll
    for (int i = 0; i < EPHW; i++)
        if (i < cnt)
            v[i] = __ldg((const float4*)((ism[i] ? g_pm : g_pg) + (size_t)s[i] * 64) + l16);
#pragma unroll
    for (int i = 0; i < EPHW; i++) {
        if (i < cnt) {
            float* p = (ism[i] ? g_sum_m : g_sum_g) + (size_t)d[i] * 64 + l16 * 4;
            asm volatile("red.global.add.v4.f32 [%0], {%1,%2,%3,%4};"
                         :: "l"(p), "f"(v[i].x), "f"(v[i].y), "f"(v[i].z), "f"(v[i].w)
                         : "memory");
            if (l16 == 0) {
                if (ism[i]) {
                    atomicAdd(g_cntm + d[i], 1.0f);
                    atomicAdd(g_pos + d[i], __ldg(bitpos + base + i));
                } else {
                    atomicAdd(g_cntg + d[i], 1.0f);
                }
            }
        }
    }
}

// ---------------- K4: node MLP (layer-1 feat part precomputed in k_feat) -> g_h ----
// smem floats: w1pos 0(64) | w2 64(8192) | b2 8256(128) -> 8384
#define NODE_SMEM (8384 * 4)
__global__ void __launch_bounds__(128) k_node_all(
    const int* __restrict__ is_po,
    const float* __restrict__ nm_w1,
    const float* __restrict__ nm_w2, const float* __restrict__ nm_b2,
    const float* __restrict__ ng_w2, const float* __restrict__ ng_b2)
{
    int nbm = (g_np[0] + 255) >> 8;
    bool MOD = (int)blockIdx.x < nbm;
    int tile = MOD ? blockIdx.x : blockIdx.x - nbm;
    int total = MOD ? g_np[0] : g_np[1];
    if (tile * 256 >= total) return;

    const float* w2 = MOD ? nm_w2 : ng_w2;
    const float* b2 = MOD ? nm_b2 : ng_b2;
    const int* perm = MOD ? g_perm_m : g_perm_g;
    const float* sums = MOD ? g_sum_m : g_sum_g;
    const float* cnts = MOD ? g_cntm : g_cntg;
    const float* hidf = MOD ? g_hidf_m : g_hidf_g;

    extern __shared__ float sm[];
    float* s_w1pos = sm;
    float* s_w2 = sm + 64;
    float* s_b2 = sm + 8256;
    {
        int t = threadIdx.x;
        for (int i = t; i < 64; i += 128) s_w1pos[i] = MOD ? nm_w1[128 * 64 + i] : 0.f;
        for (int i = t; i < 8192; i += 128) s_w2[i] = w2[i];
        for (int i = t; i < 128; i += 128) s_b2[i] = b2[i];
    }
    __syncthreads();

    int t0 = tile * 256 + threadIdx.x;
    if (t0 >= total) return;
    int t1 = t0 + 128;
    bool v1 = t1 < total;
    int t1c = v1 ? t1 : t0;
    int nda = perm[t0];
    int ndb = v1 ? perm[t1] : nda;

    float inva = 1.0f / fmaxf(cnts[nda], 1.0f);
    float invb = 1.0f / fmaxf(cnts[ndb], 1.0f);
    const u64* sra = (const u64*)(sums + (size_t)nda * 64);
    const u64* srb = (const u64*)(sums + (size_t)ndb * 64);
    const u64* hfa = (const u64*)(hidf + (size_t)t0 * 64);
    const u64* hfb = (const u64*)(hidf + (size_t)t1c * 64);

    u64 ha[32], hb[32];
    {
        u64 iva = pack2(inva, inva), ivb = pack2(invb, invb);
#pragma unroll
        for (int i = 0; i < 32; i++) {
            u64 a = hfa[i], b = hfb[i];
            fma2(a, iva, __ldg(sra + i));
            fma2(b, ivb, __ldg(srb + i));
            ha[i] = a; hb[i] = b;
        }
    }
    if (MOD) {
        float posa = g_pos[nda] * inva;
        float posb = g_pos[ndb] * invb;
        l1in2(ha, hb, posa, posb, s_w1pos);
    }
    leaky_pack(ha);
    leaky_pack(hb);

    bool keepa = (__ldg(is_po + nda) != 1);
    bool keepb = (__ldg(is_po + ndb) != 1);
    float* ora = g_h + (size_t)nda * 128;
    float* orb = g_h + (size_t)ndb * 128;
    u64 aa[16], ab[16];
#pragma unroll 1
    for (int c = 0; c < 4; c++) {
        layer2_chunk2<128>(ha, hb, s_w2, s_b2, c * 32, aa, ab);
        u64* oa = (u64*)(ora + c * 32);
#pragma unroll
        for (int i = 0; i < 16; i++) {
            float x, y; unpack2(aa[i], x, y);
            if (keepa) { x = fmaxf(x, 0.f); y = fmaxf(y, 0.f); }
            oa[i] = pack2(x, y);
        }
        if (v1) {
            u64* ob = (u64*)(orb + c * 32);
#pragma unroll
            for (int i = 0; i < 16; i++) {
                float x, y; unpack2(ab[i], x, y);
                if (keepb) { x = fmaxf(x, 0.f); y = fmaxf(y, 0.f); }
                ob[i] = pack2(x, y);
            }
        }
    }
}

// ---------------- K5: readout, hidden-half split ----------------
// smem floats: w1h 0..8191 | A 8192 (65*66=4290) | B 12482 (4290) |
//              b1 16772(64) | w2 16836(64) | knots 16900(64) -> 16964 floats
#define SM_A 8192
#define SM_B 12482
#define SM_B1 16772
#define SM_W2 16836
#define SM_KN 16900
#define OUT_SMEM (16964 * 4)
__global__ void __launch_bounds__(128) k_out(
    const float* __restrict__ o_w1, const float* __restrict__ o_b1,
    const float* __restrict__ o_w2, const float* __restrict__ level,
    float* __restrict__ out, int n)
{
    int half = blockIdx.x & 1;
    int nb = blockIdx.x >> 1;

    extern __shared__ float sm[];
    for (int i = threadIdx.x; i < 8192; i += 128) {
        int row = i >> 6, col = i & 63;
        sm[i] = o_w1[row * 128 + half * 64 + col];
    }
    for (int i = threadIdx.x; i < 65 * 64; i += 128) {
        int seg = i >> 6, col = i & 63;
        sm[SM_A + seg * 66 + col] = g_A[seg * 128 + half * 64 + col];
        sm[SM_B + seg * 66 + col] = g_B[seg * 128 + half * 64 + col];
    }
    for (int i = threadIdx.x; i < 64; i += 128) {
        sm[SM_B1 + i] = o_b1[half * 64 + i];
        sm[SM_W2 + i] = o_w2[half * 64 + i];
        sm[SM_KN + i] = g_knots[i];
    }
    __syncthreads();

    int nd0 = nb * 256 + threadIdx.x;
    if (nd0 >= n) return;
    int nd1 = nd0 + 128;
    bool v1 = nd1 < n;
    int nd1c = v1 ? nd1 : nd0;

    float lva = __ldg(level + nd0);
    float lvb = __ldg(level + nd1c);
    int sa = 0, sb = 0;
#pragma unroll
    for (int k = 0; k < 64; k++) {
        float kn = sm[SM_KN + k];
        sa += (kn < lva) ? 1 : 0;
        sb += (kn < lvb) ? 1 : 0;
    }

    u64 aa[32], ab[32];
    {
        const float* Aa = sm + SM_A + sa * 66;
        const float* Ba = sm + SM_B + sa * 66;
        const float* Ab = sm + SM_A + sb * 66;
        const float* Bb = sm + SM_B + sb * 66;
        const float* br = sm + SM_B1;
#pragma unroll
        for (int i = 0; i < 32; i++) {
            float a0 = fmaf(Aa[2 * i], lva, br[2 * i] + Ba[2 * i]);
            float a1 = fmaf(Aa[2 * i + 1], lva, br[2 * i + 1] + Ba[2 * i + 1]);
            aa[i] = pack2(a0, a1);
            float b0 = fmaf(Ab[2 * i], lvb, br[2 * i] + Bb[2 * i]);
            float b1 = fmaf(Ab[2 * i + 1], lvb, br[2 * i + 1] + Bb[2 * i + 1]);
            ab[i] = pack2(b0, b1);
        }
    }
    const float4* xa = (const float4*)(g_h + (size_t)nd0 * 128);
    const float4* xb = (const float4*)(g_h + (size_t)nd1c * 128);
#pragma unroll 2
    for (int k4 = 0; k4 < 32; k4++) {
        float4 va = __ldg(xa + k4);
        float4 vb = __ldg(xb + k4);
        const float* wr = sm + (k4 * 4) * 64;
        l1in2(aa, ab, va.x, vb.x, wr);
        l1in2(aa, ab, va.y, vb.y, wr + 64);
        l1in2(aa, ab, va.z, vb.z, wr + 128);
        l1in2(aa, ab, va.w, vb.w, wr + 192);
    }
    float ra = 0.f, rb = 0.f;
#pragma unroll
    for (int i = 0; i < 32; i++) {
        float x, y; unpack2(aa[i], x, y);
        ra += leaky(x) * sm[SM_W2 + 2 * i] + leaky(y) * sm[SM_W2 + 2 * i + 1];
        unpack2(ab[i], x, y);
        rb += leaky(x) * sm[SM_W2 + 2 * i] + leaky(y) * sm[SM_W2 + 2 * i + 1];
    }
    atomicAdd(out + nd0, ra);
    if (v1) atomicAdd(out + nd1, rb);
}

// ---------------- host launch ----------------
extern "C" void kernel_launch(void* const* d_in, const int* in_sizes, int n_in,
                              void* d_out, int out_size)
{
    const float* feat    = (const float*)d_in[0];
    const float* pi_feat = (const float*)d_in[1];
    const float* level   = (const float*)d_in[2];
    const float* bitpos  = (const float*)d_in[3];

    const int *is_po, *is_module, *src_m, *dst_m, *src_g, *dst_g;
    const float *pi_w1, *pi_b1, *pi_w2, *pi_b2;
    const float *nm_w1, *nm_b1, *nm_w2, *nm_b2;
    const float *ng_w1, *ng_b1, *ng_w2, *ng_b2;
    const float *gw1, *gb1, *gw2, *gb2;
    const float *o_w1, *o_b1, *o_w2, *o_b2;
    int Em, Eg;

    if (in_sizes[4] < 1000) {
        // reference-signature order
        pi_w1 = (const float*)d_in[4];  pi_b1 = (const float*)d_in[5];
        pi_w2 = (const float*)d_in[6];  pi_b2 = (const float*)d_in[7];
        nm_w1 = (const float*)d_in[8];  nm_b1 = (const float*)d_in[9];
        nm_w2 = (const float*)d_in[10]; nm_b2 = (const float*)d_in[11];
        ng_w1 = (const float*)d_in[12]; ng_b1 = (const float*)d_in[13];
        ng_w2 = (const float*)d_in[14]; ng_b2 = (const float*)d_in[15];
        gw1 = (const float*)d_in[16];   gb1 = (const float*)d_in[17];
        gw2 = (const float*)d_in[18];   gb2 = (const float*)d_in[19];
        o_w1 = (const float*)d_in[20];  o_b1 = (const float*)d_in[21];
        o_w2 = (const float*)d_in[22];  o_b2 = (const float*)d_in[23];
        is_po = (const int*)d_in[24];   is_module = (const int*)d_in[25];
        src_m = (const int*)d_in[26];   dst_m = (const int*)d_in[27];
        src_g = (const int*)d_in[28];   dst_g = (const int*)d_in[29];
        Em = in_sizes[26]; Eg = in_sizes[28];
    } else {
        // setup_inputs dict order
        is_po = (const int*)d_in[4];    is_module = (const int*)d_in[5];
        src_m = (const int*)d_in[6];    dst_m = (const int*)d_in[7];
        src_g = (const int*)d_in[8];    dst_g = (const int*)d_in[9];
        pi_w1 = (const float*)d_in[10]; pi_b1 = (const float*)d_in[11];
        pi_w2 = (const float*)d_in[12]; pi_b2 = (const float*)d_in[13];
        nm_w1 = (const float*)d_in[14]; nm_b1 = (const float*)d_in[15];
        nm_w2 = (const float*)d_in[16]; nm_b2 = (const float*)d_in[17];
        ng_w1 = (const float*)d_in[18]; ng_b1 = (const float*)d_in[19];
        ng_w2 = (const float*)d_in[20]; ng_b2 = (const float*)d_in[21];
        gw1 = (const float*)d_in[22];   gb1 = (const float*)d_in[23];
        gw2 = (const float*)d_in[24];   gb2 = (const float*)d_in[25];
        o_w1 = (const float*)d_in[26];  o_b1 = (const float*)d_in[27];
        o_w2 = (const float*)d_in[28];  o_b2 = (const float*)d_in[29];
        Em = in_sizes[6]; Eg = in_sizes[8];
    }

    int n = in_sizes[2];  // level has N elements

    // one-time resources (host-side; no device allocation)
    static cudaStream_t s2 = nullptr;
    static cudaEvent_t evFork = nullptr, evZero = nullptr, evB = nullptr;
    if (!s2) {
        cudaStreamCreate(&s2);
        cudaEventCreateWithFlags(&evFork, cudaEventDisableTiming);
        cudaEventCreateWithFlags(&evZero, cudaEventDisableTiming);
        cudaEventCreateWithFlags(&evB, cudaEventDisableTiming);
    }

    cudaFuncSetAttribute(k_pre, cudaFuncAttributeMaxDynamicSharedMemorySize, PRE_SMEM);
    cudaFuncSetAttribute(k_feat, cudaFuncAttributeMaxDynamicSharedMemorySize, FEAT_SMEM);
    cudaFuncSetAttribute(k_node_all, cudaFuncAttributeMaxDynamicSharedMemorySize, NODE_SMEM);
    cudaFuncSetAttribute(k_out, cudaFuncAttributeMaxDynamicSharedMemorySize, OUT_SMEM);

    int ntile = (n + 255) / 256;          // 256-node tiles
    int npart = (n + 255) / 256;          // part blocks

    void *p_sum_m, *p_sum_g, *p_np;
    cudaGetSymbolAddress(&p_sum_m, g_sum_m);
    cudaGetSymbolAddress(&p_sum_g, g_sum_g);
    cudaGetSymbolAddress(&p_np, g_np);

    // fork side stream into capture
    cudaEventRecord(evFork, 0);
    cudaStreamWaitEvent(s2, evFork, 0);

    // ---- side stream B: zero + partition + feat projection
    cudaMemsetAsync(p_sum_m, 0, (size_t)n * 64 * 4, s2);
    cudaMemsetAsync(p_sum_g, 0, (size_t)n * 64 * 4, s2);
    cudaMemsetAsync(p_np, 0, 8, s2);
    k_part<<<npart, 256, 0, s2>>>(is_module, n);
    cudaEventRecord(evZero, s2);    // sums + per-node scalars all zeroed
    k_feat<<<ntile + 1, 128, FEAT_SMEM, s2>>>(feat, nm_w1, nm_b1, ng_w1, ng_b1);
    cudaEventRecord(evB, s2);

    // ---- main stream A
    k_compose<<<dim3(65, 2), 64>>>(pi_w2, pi_b2, nm_w1, ng_w1);
    k_pre<<<65 + ntile, 128, PRE_SMEM>>>(
        pi_feat, pi_w1, pi_b1,
        gw1, gb1, gw2, gb2, o_w1,
        o_b2, (float*)d_out, n);

    cudaStreamWaitEvent(0, evZero, 0);
    long long Etot = (long long)Em + Eg;
    long long hws = (Etot + EPHW - 1) / EPHW;
    int eb = (int)((hws * 16 + 255) / 256);
    k_edges_all<<<eb, 256>>>(src_m, dst_m, src_g, dst_g, bitpos, Em, Eg);

    cudaStreamWaitEvent(0, evB, 0);
    k_node_all<<<ntile + 1, 128, NODE_SMEM>>>(
        is_po, nm_w1, nm_w2, nm_b2, ng_w2, ng_b2);

    k_out<<<ntile * 2, 128, OUT_SMEM>>>(
        o_w1, o_b1, o_w2, level, (float*)d_out, n);
}